// round 4
// baseline (speedup 1.0000x reference)
#include <cuda_runtime.h>
#include <cstdint>

// LogicLayer: out[i,j] = g_a(x[i,idx_a[j]]) * g_b(x[i,idx_b[j]])
//   g(v) = (logit > 0) ? 1-v : v
//
// R3 changes vs R2 (92.6us, L1=76% smem-bound):
//  - prep_balance: per 32-j gather group, greedily swap (a,b) operand halves
//    (product is commutative) to balance smem banks across the two LDS
//    instructions -> conflict degree ~3.3 -> ~2.5, zero runtime cost.
//  - TMA bulk staging of the 128KiB x-row (no LDG/STS wavefronts, mbarrier wait).
//  - scalar j = k*1024 + t layout: gather groups are contiguous 32-j runs
//    matching prep_balance's grouping; stores stay fully coalesced.

#define IN_DIM   32768
#define OUT_DIM  32768
#define BATCH    1024
#define NTHREADS 1024
#define ITERS    (OUT_DIM / NTHREADS)  // 32

__device__ uint32_t g_packed[OUT_DIM];

// ---------------- prep 1: pack (fa|ia | fb|ib) into one u32 per j -------------
__global__ void prep_pack(const float* __restrict__ logits,
                          const int* __restrict__ idx_a,
                          const int* __restrict__ idx_b) {
    int j = blockIdx.x * blockDim.x + threadIdx.x;
    if (j >= OUT_DIM) return;
    uint32_t ia = (uint32_t)idx_a[j] & 0x7FFFu;
    uint32_t ib = (uint32_t)idx_b[j] & 0x7FFFu;
    uint32_t fa = (logits[2 * j]     > 0.0f) ? 1u : 0u;
    uint32_t fb = (logits[2 * j + 1] > 0.0f) ? 1u : 0u;
    // hi16 = (fa<<15)|ia, lo16 = (fb<<15)|ib  -> operand swap == 16-bit rotate
    g_packed[j] = (fa << 31) | (ia << 16) | (fb << 15) | ib;
}

// ---------------- prep 2: per-group operand-swap bank balancing ---------------
// Gather group = 32 consecutive j's (one warp iteration in the main kernel).
// LDS#1 reads the hi16 operand of each lane, LDS#2 the lo16 operand.
// Greedily choose per-lane swap to minimize per-instruction max bank load.
// Counters: 32 banks x 4-bit saturating nibbles packed in 2x u64 per instr.
__device__ __forceinline__ uint32_t nib_get(uint64_t lo, uint64_t hi, uint32_t b) {
    uint64_t w = (b < 16) ? lo : hi;
    return (uint32_t)(w >> ((b & 15u) * 4)) & 15u;
}
__device__ __forceinline__ void nib_inc(uint64_t& lo, uint64_t& hi, uint32_t b) {
    uint32_t cur = nib_get(lo, hi, b);
    if (cur >= 15u) return;  // saturate
    uint64_t add = 1ull << ((b & 15u) * 4);
    if (b < 16) lo += add; else hi += add;
}

__global__ void prep_balance() {
    int g = blockIdx.x * blockDim.x + threadIdx.x;
    if (g >= OUT_DIM / 32) return;
    uint64_t c0lo = 0, c0hi = 0;  // bank loads of LDS#1 (hi16 operands)
    uint64_t c1lo = 0, c1hi = 0;  // bank loads of LDS#2 (lo16 operands)
    const int base = g * 32;
    #pragma unroll 4
    for (int l = 0; l < 32; l++) {
        uint32_t p  = g_packed[base + l];
        uint32_t ba = (p >> 16) & 31u;  // bank of hi operand
        uint32_t bb = p & 31u;          // bank of lo operand
        uint32_t costA = max(nib_get(c0lo, c0hi, ba), nib_get(c1lo, c1hi, bb));
        uint32_t costB = max(nib_get(c0lo, c0hi, bb), nib_get(c1lo, c1hi, ba));
        if (costB < costA) {
            g_packed[base + l] = __funnelshift_l(p, p, 16);  // swap operands
            nib_inc(c0lo, c0hi, bb);
            nib_inc(c1lo, c1hi, ba);
        } else {
            nib_inc(c0lo, c0hi, ba);
            nib_inc(c1lo, c1hi, bb);
        }
    }
}

// ---------------- main kernel: TMA-stage row, gather from smem ----------------
__device__ __forceinline__ uint32_t smem_u32(const void* p) {
    uint32_t a;
    asm("{ .reg .u64 t; cvta.to.shared.u64 t, %1; cvt.u32.u64 %0, t; }"
        : "=r"(a) : "l"(p));
    return a;
}

__global__ __launch_bounds__(NTHREADS, 1)
void logic_layer_kernel(const float* __restrict__ x,
                        float* __restrict__ out) {
    extern __shared__ float sx[];
    __shared__ __align__(8) uint64_t mbar;

    const int row = blockIdx.x;
    const uint32_t mbar_a = smem_u32(&mbar);
    const uint32_t dst_a  = smem_u32(sx);

    if (threadIdx.x == 0) {
        asm volatile("mbarrier.init.shared.b64 [%0], 1;" :: "r"(mbar_a) : "memory");
        asm volatile("fence.proxy.async.shared::cta;" ::: "memory");
    }
    __syncthreads();

    if (threadIdx.x == 0) {
        asm volatile("mbarrier.arrive.expect_tx.shared.b64 _, [%0], %1;"
                     :: "r"(mbar_a), "r"((uint32_t)(IN_DIM * 4)) : "memory");
        asm volatile("cp.async.bulk.shared::cta.global.mbarrier::complete_tx::bytes "
                     "[%0], [%1], %2, [%3];"
                     :: "r"(dst_a), "l"(x + (size_t)row * IN_DIM),
                        "r"((uint32_t)(IN_DIM * 4)), "r"(mbar_a)
                     : "memory");
    }

    // wait for the row to land (acquire orders subsequent LDS)
    {
        uint32_t done;
        asm volatile(
            "{\n\t.reg .pred P;\n\t"
            "mbarrier.try_wait.parity.acquire.cta.shared::cta.b64 P, [%1], 0, 0x989680;\n\t"
            "selp.b32 %0, 1, 0, P;\n\t}"
            : "=r"(done) : "r"(mbar_a) : "memory");
        if (!done) {
            asm volatile(
                "{\n\t.reg .pred P;\n"
                "WL_%=:\n\t"
                "mbarrier.try_wait.parity.acquire.cta.shared::cta.b64 P, [%0], 0, 0x989680;\n\t"
                "@P bra.uni WD_%=;\n\t"
                "bra.uni WL_%=;\n"
                "WD_%=:\n\t}"
                :: "r"(mbar_a) : "memory");
        }
    }

    float* orow = out + (size_t)row * OUT_DIM;
    const int t = threadIdx.x;

    #pragma unroll 8
    for (int k = 0; k < ITERS; k++) {
        int j = k * NTHREADS + t;
        uint32_t p = g_packed[j];
        float a = sx[(p >> 16) & 0x7FFFu];
        float b = sx[p & 0x7FFFu];
        if (p & 0x80000000u) a = 1.0f - a;
        if (p & 0x00008000u) b = 1.0f - b;
        orow[j] = a * b;
    }
}

extern "C" void kernel_launch(void* const* d_in, const int* in_sizes, int n_in,
                              void* d_out, int out_size) {
    const float* x      = (const float*)d_in[0];
    const float* logits = (const float*)d_in[1];
    const int*   idx_a  = (const int*)d_in[2];
    const int*   idx_b  = (const int*)d_in[3];
    float* out = (float*)d_out;

    cudaFuncSetAttribute(logic_layer_kernel,
                         cudaFuncAttributeMaxDynamicSharedMemorySize,
                         IN_DIM * (int)sizeof(float));

    prep_pack<<<(OUT_DIM + 255) / 256, 256>>>(logits, idx_a, idx_b);
    prep_balance<<<(OUT_DIM / 32 + 255) / 256, 256>>>();
    logic_layer_kernel<<<BATCH, NTHREADS, IN_DIM * sizeof(float)>>>(x, out);
}

// round 5
// speedup vs baseline: 1.2634x; 1.2634x over previous
#include <cuda_runtime.h>
#include <cstdint>

// LogicLayer: out[i,j] = g_a(x[i,idx_a[j]]) * g_b(x[i,idx_b[j]])
//   g(v) = (logit > 0) ? 1-v : v
//
// R5 vs R4 (88.6us):
//  - main loop: 4-deep register ring prefetch of packed words (kills exposed
//    L2 latency; kernel was issue/latency-bound at issue=23%, not port-bound)
//  - fully unrolled 32-iteration gather loop
//  - prep_pack + prep_balance merged into one kernel (smem staging)

#define IN_DIM   32768
#define OUT_DIM  32768
#define BATCH    1024
#define NTHREADS 1024
#define ITERS    (OUT_DIM / NTHREADS)  // 32

__device__ uint32_t g_packed[OUT_DIM];

// ---------------- prep: pack + per-group operand-swap bank balance -----------
// Gather group = 32 consecutive j (one warp instruction in the main kernel).
// Product is commutative, so per j we may swap the (flag,idx) halves; greedy
// swap balances smem banks across the two LDS instructions of the group.

__device__ __forceinline__ uint32_t nib_get(uint64_t lo, uint64_t hi, uint32_t b) {
    uint64_t w = (b < 16) ? lo : hi;
    return (uint32_t)(w >> ((b & 15u) * 4)) & 15u;
}
__device__ __forceinline__ void nib_inc(uint64_t& lo, uint64_t& hi, uint32_t b) {
    if (nib_get(lo, hi, b) >= 15u) return;
    uint64_t add = 1ull << ((b & 15u) * 4);
    if (b < 16) lo += add; else hi += add;
}

__global__ void prep_kernel(const float* __restrict__ logits,
                            const int* __restrict__ idx_a,
                            const int* __restrict__ idx_b) {
    __shared__ uint32_t sp[1024];
    const int blk = blockIdx.x;        // 32 blocks x 1024 j
    const int t = threadIdx.x;         // 256 threads

    #pragma unroll
    for (int q = 0; q < 4; q++) {
        int jl = t + q * 256;
        int j  = blk * 1024 + jl;
        uint32_t ia = (uint32_t)idx_a[j] & 0x7FFFu;
        uint32_t ib = (uint32_t)idx_b[j] & 0x7FFFu;
        uint32_t fa = (logits[2 * j]     > 0.0f) ? 1u : 0u;
        uint32_t fb = (logits[2 * j + 1] > 0.0f) ? 1u : 0u;
        sp[jl] = (fa << 31) | (ia << 16) | (fb << 15) | ib;
    }
    __syncthreads();

    if (t < 32) {
        // balance group t: sp[t*32 .. t*32+32)
        uint64_t c0lo = 0, c0hi = 0;   // LDS#1 (hi16 operand) bank loads
        uint64_t c1lo = 0, c1hi = 0;   // LDS#2 (lo16 operand) bank loads
        const int base = t * 32;
        #pragma unroll 4
        for (int l = 0; l < 32; l++) {
            uint32_t p  = sp[base + l];
            uint32_t ba = (p >> 16) & 31u;
            uint32_t bb = p & 31u;
            uint32_t costA = max(nib_get(c0lo, c0hi, ba), nib_get(c1lo, c1hi, bb));
            uint32_t costB = max(nib_get(c0lo, c0hi, bb), nib_get(c1lo, c1hi, ba));
            if (costB < costA) {
                sp[base + l] = __funnelshift_l(p, p, 16);
                nib_inc(c0lo, c0hi, bb);
                nib_inc(c1lo, c1hi, ba);
            } else {
                nib_inc(c0lo, c0hi, ba);
                nib_inc(c1lo, c1hi, bb);
            }
        }
    }
    __syncthreads();

    #pragma unroll
    for (int q = 0; q < 4; q++) {
        int jl = t + q * 256;
        g_packed[blk * 1024 + jl] = sp[jl];
    }
}

// ---------------- main kernel: TMA-stage row, gather from smem ---------------
__device__ __forceinline__ uint32_t smem_u32(const void* p) {
    uint32_t a;
    asm("{ .reg .u64 t; cvta.to.shared.u64 t, %1; cvt.u32.u64 %0, t; }"
        : "=r"(a) : "l"(p));
    return a;
}

__global__ __launch_bounds__(NTHREADS, 1)
void logic_layer_kernel(const float* __restrict__ x,
                        float* __restrict__ out) {
    extern __shared__ float sx[];
    __shared__ __align__(8) uint64_t mbar;

    const int row = blockIdx.x;
    const uint32_t mbar_a = smem_u32(&mbar);
    const uint32_t dst_a  = smem_u32(sx);

    if (threadIdx.x == 0) {
        asm volatile("mbarrier.init.shared.b64 [%0], 1;" :: "r"(mbar_a) : "memory");
        asm volatile("fence.proxy.async.shared::cta;" ::: "memory");
    }
    __syncthreads();

    if (threadIdx.x == 0) {
        asm volatile("mbarrier.arrive.expect_tx.shared.b64 _, [%0], %1;"
                     :: "r"(mbar_a), "r"((uint32_t)(IN_DIM * 4)) : "memory");
        asm volatile("cp.async.bulk.shared::cta.global.mbarrier::complete_tx::bytes "
                     "[%0], [%1], %2, [%3];"
                     :: "r"(dst_a), "l"(x + (size_t)row * IN_DIM),
                        "r"((uint32_t)(IN_DIM * 4)), "r"(mbar_a)
                     : "memory");
    }

    const int t = threadIdx.x;
    float* orow = out + (size_t)row * OUT_DIM;

    // Prefetch first 4 packed words while the TMA fill is in flight.
    uint32_t pr[4];
    #pragma unroll
    for (int k = 0; k < 4; k++) pr[k] = g_packed[k * NTHREADS + t];

    // Wait for the row to land (acquire orders subsequent LDS).
    {
        uint32_t done;
        asm volatile(
            "{\n\t.reg .pred P;\n\t"
            "mbarrier.try_wait.parity.acquire.cta.shared::cta.b64 P, [%1], 0, 0x989680;\n\t"
            "selp.b32 %0, 1, 0, P;\n\t}"
            : "=r"(done) : "r"(mbar_a) : "memory");
        if (!done) {
            asm volatile(
                "{\n\t.reg .pred P;\n"
                "WL_%=:\n\t"
                "mbarrier.try_wait.parity.acquire.cta.shared::cta.b64 P, [%0], 0, 0x989680;\n\t"
                "@P bra.uni WD_%=;\n\t"
                "bra.uni WL_%=;\n"
                "WD_%=:\n\t}"
                :: "r"(mbar_a) : "memory");
        }
    }

    // Fully unrolled gather loop with 4-deep packed-word prefetch ring.
    #pragma unroll
    for (int k = 0; k < ITERS; k++) {
        uint32_t p = pr[k & 3];
        if (k + 4 < ITERS) pr[k & 3] = g_packed[(k + 4) * NTHREADS + t];
        float a = sx[(p >> 16) & 0x7FFFu];
        float b = sx[p & 0x7FFFu];
        if (p & 0x80000000u) a = 1.0f - a;
        if (p & 0x00008000u) b = 1.0f - b;
        orow[k * NTHREADS + t] = a * b;
    }
}

extern "C" void kernel_launch(void* const* d_in, const int* in_sizes, int n_in,
                              void* d_out, int out_size) {
    const float* x      = (const float*)d_in[0];
    const float* logits = (const float*)d_in[1];
    const int*   idx_a  = (const int*)d_in[2];
    const int*   idx_b  = (const int*)d_in[3];
    float* out = (float*)d_out;

    cudaFuncSetAttribute(logic_layer_kernel,
                         cudaFuncAttributeMaxDynamicSharedMemorySize,
                         IN_DIM * (int)sizeof(float));

    prep_kernel<<<OUT_DIM / 1024, 256>>>(logits, idx_a, idx_b);
    logic_layer_kernel<<<BATCH, NTHREADS, IN_DIM * sizeof(float)>>>(x, out);
}

// round 6
// speedup vs baseline: 1.2959x; 1.0257x over previous
#include <cuda_runtime.h>
#include <cstdint>

// LogicLayer: out[i,j] = g_a(x[i,idx_a[j]]) * g_b(x[i,idx_b[j]])
//   g(v) = (logit > 0) ? 1-v : v
//
// R6 vs R5 (70.1us = 58.9 main + ~11 prep):
//  - main: prefetch ALL 32 packed words to registers before the TMA wait
//    (loop body = pure LDS/FFMA/STG, no gmem latency), paired iterations
//    for explicit LDS MLP, streaming stores (.cs).
//  - prep: 1024 blocks x 32 threads (was 32 blocks) — full-chip spread,
//    ~1us serial greedy per group instead of a 11us tail.

#define IN_DIM   32768
#define OUT_DIM  32768
#define BATCH    1024
#define NTHREADS 1024
#define ITERS    (OUT_DIM / NTHREADS)  // 32

__device__ uint32_t g_packed[OUT_DIM];

// ---------------- prep: pack + per-group operand-swap bank balance -----------
// Group = 32 consecutive j (one warp instruction in the main kernel).
// Product commutative -> may swap (flag,idx) halves per j; greedy swap
// balances smem banks across the group's two LDS instructions.

__device__ __forceinline__ uint32_t nib_get(uint64_t lo, uint64_t hi, uint32_t b) {
    uint64_t w = (b < 16) ? lo : hi;
    return (uint32_t)(w >> ((b & 15u) * 4)) & 15u;
}
__device__ __forceinline__ void nib_inc(uint64_t& lo, uint64_t& hi, uint32_t b) {
    if (nib_get(lo, hi, b) >= 15u) return;
    uint64_t add = 1ull << ((b & 15u) * 4);
    if (b < 16) lo += add; else hi += add;
}

__global__ __launch_bounds__(32, 16)
void prep_kernel(const float* __restrict__ logits,
                 const int* __restrict__ idx_a,
                 const int* __restrict__ idx_b) {
    __shared__ uint32_t sp[32];
    const int g = blockIdx.x;          // 1024 groups
    const int lane = threadIdx.x;      // 32 threads
    const int j = g * 32 + lane;

    uint32_t ia = (uint32_t)idx_a[j] & 0x7FFFu;
    uint32_t ib = (uint32_t)idx_b[j] & 0x7FFFu;
    uint32_t fa = (logits[2 * j]     > 0.0f) ? 1u : 0u;
    uint32_t fb = (logits[2 * j + 1] > 0.0f) ? 1u : 0u;
    sp[lane] = (fa << 31) | (ia << 16) | (fb << 15) | ib;
    __syncwarp();

    if (lane == 0) {
        uint64_t c0lo = 0, c0hi = 0;   // LDS#1 (hi16 operand) bank loads
        uint64_t c1lo = 0, c1hi = 0;   // LDS#2 (lo16 operand) bank loads
        #pragma unroll 4
        for (int l = 0; l < 32; l++) {
            uint32_t p  = sp[l];
            uint32_t ba = (p >> 16) & 31u;
            uint32_t bb = p & 31u;
            uint32_t costA = max(nib_get(c0lo, c0hi, ba), nib_get(c1lo, c1hi, bb));
            uint32_t costB = max(nib_get(c0lo, c0hi, bb), nib_get(c1lo, c1hi, ba));
            if (costB < costA) {
                sp[l] = __funnelshift_l(p, p, 16);
                nib_inc(c0lo, c0hi, bb);
                nib_inc(c1lo, c1hi, ba);
            } else {
                nib_inc(c0lo, c0hi, ba);
                nib_inc(c1lo, c1hi, bb);
            }
        }
    }
    __syncwarp();
    g_packed[j] = sp[lane];
}

// ---------------- main kernel: TMA-stage row, gather from smem ---------------
__device__ __forceinline__ uint32_t smem_u32(const void* p) {
    uint32_t a;
    asm("{ .reg .u64 t; cvta.to.shared.u64 t, %1; cvt.u32.u64 %0, t; }"
        : "=r"(a) : "l"(p));
    return a;
}

__device__ __forceinline__ void stg_cs(float* p, float v) {
    asm volatile("st.global.cs.f32 [%0], %1;" :: "l"(p), "f"(v) : "memory");
}

__global__ __launch_bounds__(NTHREADS, 1)
void logic_layer_kernel(const float* __restrict__ x,
                        float* __restrict__ out) {
    extern __shared__ float sx[];
    __shared__ __align__(8) uint64_t mbar;

    const int row = blockIdx.x;
    const uint32_t mbar_a = smem_u32(&mbar);
    const uint32_t dst_a  = smem_u32(sx);

    if (threadIdx.x == 0) {
        asm volatile("mbarrier.init.shared.b64 [%0], 1;" :: "r"(mbar_a) : "memory");
        asm volatile("fence.proxy.async.shared::cta;" ::: "memory");
    }
    __syncthreads();

    if (threadIdx.x == 0) {
        asm volatile("mbarrier.arrive.expect_tx.shared.b64 _, [%0], %1;"
                     :: "r"(mbar_a), "r"((uint32_t)(IN_DIM * 4)) : "memory");
        asm volatile("cp.async.bulk.shared::cta.global.mbarrier::complete_tx::bytes "
                     "[%0], [%1], %2, [%3];"
                     :: "r"(dst_a), "l"(x + (size_t)row * IN_DIM),
                        "r"((uint32_t)(IN_DIM * 4)), "r"(mbar_a)
                     : "memory");
    }

    const int t = threadIdx.x;
    float* orow = out + (size_t)row * OUT_DIM;

    // Prefetch ALL packed words while the TMA fill streams in.
    uint32_t pr[ITERS];
    #pragma unroll
    for (int k = 0; k < ITERS; k++) pr[k] = g_packed[k * NTHREADS + t];

    // Wait for the row to land (acquire orders subsequent LDS).
    {
        uint32_t done;
        asm volatile(
            "{\n\t.reg .pred P;\n\t"
            "mbarrier.try_wait.parity.acquire.cta.shared::cta.b64 P, [%1], 0, 0x989680;\n\t"
            "selp.b32 %0, 1, 0, P;\n\t}"
            : "=r"(done) : "r"(mbar_a) : "memory");
        if (!done) {
            asm volatile(
                "{\n\t.reg .pred P;\n"
                "WL_%=:\n\t"
                "mbarrier.try_wait.parity.acquire.cta.shared::cta.b64 P, [%0], 0, 0x989680;\n\t"
                "@P bra.uni WD_%=;\n\t"
                "bra.uni WL_%=;\n"
                "WD_%=:\n\t}"
                :: "r"(mbar_a) : "memory");
        }
    }

    // Pure-LDS gather loop, two independent iterations per body for MLP.
    #pragma unroll
    for (int k = 0; k < ITERS; k += 2) {
        uint32_t p0 = pr[k], p1 = pr[k + 1];
        float a0 = sx[(p0 >> 16) & 0x7FFFu];
        float b0 = sx[p0 & 0x7FFFu];
        float a1 = sx[(p1 >> 16) & 0x7FFFu];
        float b1 = sx[p1 & 0x7FFFu];
        if (p0 & 0x80000000u) a0 = 1.0f - a0;
        if (p0 & 0x00008000u) b0 = 1.0f - b0;
        if (p1 & 0x80000000u) a1 = 1.0f - a1;
        if (p1 & 0x00008000u) b1 = 1.0f - b1;
        stg_cs(&orow[k * NTHREADS + t], a0 * b0);
        stg_cs(&orow[(k + 1) * NTHREADS + t], a1 * b1);
    }
}

extern "C" void kernel_launch(void* const* d_in, const int* in_sizes, int n_in,
                              void* d_out, int out_size) {
    const float* x      = (const float*)d_in[0];
    const float* logits = (const float*)d_in[1];
    const int*   idx_a  = (const int*)d_in[2];
    const int*   idx_b  = (const int*)d_in[3];
    float* out = (float*)d_out;

    cudaFuncSetAttribute(logic_layer_kernel,
                         cudaFuncAttributeMaxDynamicSharedMemorySize,
                         IN_DIM * (int)sizeof(float));

    prep_kernel<<<OUT_DIM / 32, 32>>>(logits, idx_a, idx_b);
    logic_layer_kernel<<<BATCH, NTHREADS, IN_DIM * sizeof(float)>>>(x, out);
}

// round 7
// speedup vs baseline: 1.4387x; 1.1102x over previous
#include <cuda_runtime.h>
#include <cstdint>

// LogicLayer: out[i,j] = g_a(x[i,idx_a[j]]) * g_b(x[i,idx_b[j]])
//   g(v) = (logit > 0) ? 1-v : v
//
// R7 vs R6 (68.4us = 56.8 main + ~11.6 prep):
//  - main: cp.async.bulk.prefetch.L2 of row (b+148) issued at CTA start ->
//    next wave's TMA fill hits L2 instead of cold DRAM; DRAM read for the
//    next row overlaps current row's gather/store. Kills the per-wave
//    ~5600-cycle fill dead time (the dominant loss at 1 CTA/SM).
//  - main: packed prefetch ring back to 8 (R6's pr[32] hit the 64-reg cap).
//  - prep: 128 blocks x 256 threads, one warp per 32-j group, greedy
//    operand-swap balance at lane 0 via shuffles (was 1024 x 32t blocks).

#define IN_DIM   32768
#define OUT_DIM  32768
#define BATCH    1024
#define NTHREADS 1024
#define ITERS    (OUT_DIM / NTHREADS)  // 32
#define NSM      148

__device__ uint32_t g_packed[OUT_DIM];

// ---------------- prep: pack + per-group operand-swap bank balance -----------
__device__ __forceinline__ uint32_t nib_get(uint64_t lo, uint64_t hi, uint32_t b) {
    uint64_t w = (b < 16) ? lo : hi;
    return (uint32_t)(w >> ((b & 15u) * 4)) & 15u;
}
__device__ __forceinline__ void nib_inc(uint64_t& lo, uint64_t& hi, uint32_t b) {
    if (nib_get(lo, hi, b) >= 15u) return;
    uint64_t add = 1ull << ((b & 15u) * 4);
    if (b < 16) lo += add; else hi += add;
}

__global__ __launch_bounds__(256)
void prep_kernel(const float* __restrict__ logits,
                 const int* __restrict__ idx_a,
                 const int* __restrict__ idx_b) {
    const int lane = threadIdx.x & 31;
    const int g = blockIdx.x * 8 + (threadIdx.x >> 5);  // group id, 1024 total
    const int j = g * 32 + lane;

    uint32_t ia = (uint32_t)idx_a[j] & 0x7FFFu;
    uint32_t ib = (uint32_t)idx_b[j] & 0x7FFFu;
    uint32_t fa = (logits[2 * j]     > 0.0f) ? 1u : 0u;
    uint32_t fb = (logits[2 * j + 1] > 0.0f) ? 1u : 0u;
    uint32_t myp = (fa << 31) | (ia << 16) | (fb << 15) | ib;

    // lane 0 runs the greedy swap over shuffled values, builds a swap mask.
    uint32_t swapmask = 0;
    uint64_t c0lo = 0, c0hi = 0;   // LDS#1 (hi16 operand) bank loads
    uint64_t c1lo = 0, c1hi = 0;   // LDS#2 (lo16 operand) bank loads
    #pragma unroll 4
    for (int l = 0; l < 32; l++) {
        uint32_t p = __shfl_sync(0xFFFFFFFFu, myp, l);
        if (lane == 0) {
            uint32_t ba = (p >> 16) & 31u;
            uint32_t bb = p & 31u;
            uint32_t costA = max(nib_get(c0lo, c0hi, ba), nib_get(c1lo, c1hi, bb));
            uint32_t costB = max(nib_get(c0lo, c0hi, bb), nib_get(c1lo, c1hi, ba));
            if (costB < costA) {
                swapmask |= (1u << l);
                nib_inc(c0lo, c0hi, bb);
                nib_inc(c1lo, c1hi, ba);
            } else {
                nib_inc(c0lo, c0hi, ba);
                nib_inc(c1lo, c1hi, bb);
            }
        }
    }
    swapmask = __shfl_sync(0xFFFFFFFFu, swapmask, 0);
    if ((swapmask >> lane) & 1u) myp = __funnelshift_l(myp, myp, 16);
    g_packed[j] = myp;
}

// ---------------- main kernel: TMA-stage row, gather from smem ---------------
__device__ __forceinline__ uint32_t smem_u32(const void* p) {
    uint32_t a;
    asm("{ .reg .u64 t; cvta.to.shared.u64 t, %1; cvt.u32.u64 %0, t; }"
        : "=r"(a) : "l"(p));
    return a;
}

__device__ __forceinline__ void stg_cs(float* p, float v) {
    asm volatile("st.global.cs.f32 [%0], %1;" :: "l"(p), "f"(v) : "memory");
}

__global__ __launch_bounds__(NTHREADS, 1)
void logic_layer_kernel(const float* __restrict__ x,
                        float* __restrict__ out) {
    extern __shared__ float sx[];
    __shared__ __align__(8) uint64_t mbar;

    const int row = blockIdx.x;
    const uint32_t mbar_a = smem_u32(&mbar);
    const uint32_t dst_a  = smem_u32(sx);

    if (threadIdx.x == 0) {
        asm volatile("mbarrier.init.shared.b64 [%0], 1;" :: "r"(mbar_a) : "memory");
        asm volatile("fence.proxy.async.shared::cta;" ::: "memory");
    }
    __syncthreads();

    if (threadIdx.x == 0) {
        asm volatile("mbarrier.arrive.expect_tx.shared.b64 _, [%0], %1;"
                     :: "r"(mbar_a), "r"((uint32_t)(IN_DIM * 4)) : "memory");
        asm volatile("cp.async.bulk.shared::cta.global.mbarrier::complete_tx::bytes "
                     "[%0], [%1], %2, [%3];"
                     :: "r"(dst_a), "l"(x + (size_t)row * IN_DIM),
                        "r"((uint32_t)(IN_DIM * 4)), "r"(mbar_a)
                     : "memory");
    }

    // Prefetch the row this SM will process next wave into L2: its DRAM read
    // overlaps this row's gather/store, and next wave's TMA fill hits L2.
    if (threadIdx.x == 32 && row + NSM < BATCH) {
        asm volatile("cp.async.bulk.prefetch.L2.global [%0], %1;"
                     :: "l"(x + (size_t)(row + NSM) * IN_DIM),
                        "r"((uint32_t)(IN_DIM * 4)) : "memory");
    }

    const int t = threadIdx.x;
    float* orow = out + (size_t)row * OUT_DIM;

    // 8-deep packed-word prefetch ring, primed while the TMA fill streams in.
    uint32_t pr[8];
    #pragma unroll
    for (int k = 0; k < 8; k++) pr[k] = g_packed[k * NTHREADS + t];

    // Wait for the row to land (acquire orders subsequent LDS).
    {
        uint32_t done;
        asm volatile(
            "{\n\t.reg .pred P;\n\t"
            "mbarrier.try_wait.parity.acquire.cta.shared::cta.b64 P, [%1], 0, 0x989680;\n\t"
            "selp.b32 %0, 1, 0, P;\n\t}"
            : "=r"(done) : "r"(mbar_a) : "memory");
        if (!done) {
            asm volatile(
                "{\n\t.reg .pred P;\n"
                "WL_%=:\n\t"
                "mbarrier.try_wait.parity.acquire.cta.shared::cta.b64 P, [%0], 0, 0x989680;\n\t"
                "@P bra.uni WD_%=;\n\t"
                "bra.uni WL_%=;\n"
                "WD_%=:\n\t}"
                :: "r"(mbar_a) : "memory");
        }
    }

    #pragma unroll
    for (int k = 0; k < ITERS; k++) {
        uint32_t p = pr[k & 7];
        if (k + 8 < ITERS) pr[k & 7] = g_packed[(k + 8) * NTHREADS + t];
        float a = sx[(p >> 16) & 0x7FFFu];
        float b = sx[p & 0x7FFFu];
        if (p & 0x80000000u) a = 1.0f - a;
        if (p & 0x00008000u) b = 1.0f - b;
        stg_cs(&orow[k * NTHREADS + t], a * b);
    }
}

extern "C" void kernel_launch(void* const* d_in, const int* in_sizes, int n_in,
                              void* d_out, int out_size) {
    const float* x      = (const float*)d_in[0];
    const float* logits = (const float*)d_in[1];
    const int*   idx_a  = (const int*)d_in[2];
    const int*   idx_b  = (const int*)d_in[3];
    float* out = (float*)d_out;

    cudaFuncSetAttribute(logic_layer_kernel,
                         cudaFuncAttributeMaxDynamicSharedMemorySize,
                         IN_DIM * (int)sizeof(float));

    prep_kernel<<<OUT_DIM / (32 * 8), 256>>>(logits, idx_a, idx_b);
    logic_layer_kernel<<<BATCH, NTHREADS, IN_DIM * sizeof(float)>>>(x, out);
}

// round 8
// speedup vs baseline: 1.4731x; 1.0239x over previous
#include <cuda_runtime.h>
#include <cstdint>

// LogicLayer: out[i,j] = g_a(x[i,idx_a[j]]) * g_b(x[i,idx_b[j]])
//   g(v) = (logit > 0) ? 1-v : v
//
// R8 vs R7 (61.6us = 53.0 main + ~8.6 prep):
//  - dropped bank-balance prep (L1 port at 52% => conflicts not binding;
//    the balance kernel cost ~7us). Prep = trivial pack, ~1.5us.
//  - persistent main kernel (grid=148): row loop with single smem buffer,
//    next-row TMA issued right after the gather-phase __syncthreads.
//    Kills 6 wave transitions + per-wave setup.
//  - float2 work granularity: uint2 packed loads, STG.64.cs stores ->
//    ~35% fewer instructions on the 27%-busy issue path.

#define IN_DIM   32768
#define OUT_DIM  32768
#define BATCH    1024
#define NTHREADS 1024
#define NSM      148
#define ITERS2   (OUT_DIM / (NTHREADS * 2))  // 16

__device__ uint32_t g_packed[OUT_DIM];

// ---------------- prep: pack (fa|ia | fb|ib) into one u32 per j --------------
__global__ __launch_bounds__(256)
void prep_kernel(const float* __restrict__ logits,
                 const int* __restrict__ idx_a,
                 const int* __restrict__ idx_b) {
    int j = blockIdx.x * 256 + threadIdx.x;
    uint32_t ia = (uint32_t)idx_a[j] & 0x7FFFu;
    uint32_t ib = (uint32_t)idx_b[j] & 0x7FFFu;
    uint32_t fa = (logits[2 * j]     > 0.0f) ? 1u : 0u;
    uint32_t fb = (logits[2 * j + 1] > 0.0f) ? 1u : 0u;
    g_packed[j] = (fa << 31) | (ia << 16) | (fb << 15) | ib;
}

// ---------------- main: persistent, TMA-stage row, gather from smem ----------
__device__ __forceinline__ uint32_t smem_u32(const void* p) {
    uint32_t a;
    asm("{ .reg .u64 t; cvta.to.shared.u64 t, %1; cvt.u32.u64 %0, t; }"
        : "=r"(a) : "l"(p));
    return a;
}

__device__ __forceinline__ void stg_cs_v2(float* p, float v0, float v1) {
    asm volatile("st.global.cs.v2.f32 [%0], {%1, %2};"
                 :: "l"(p), "f"(v0), "f"(v1) : "memory");
}

__device__ __forceinline__ void mbar_wait(uint32_t mbar_a, uint32_t phase) {
    uint32_t done;
    asm volatile(
        "{\n\t.reg .pred P;\n\t"
        "mbarrier.try_wait.parity.acquire.cta.shared::cta.b64 P, [%1], %2, 0x989680;\n\t"
        "selp.b32 %0, 1, 0, P;\n\t}"
        : "=r"(done) : "r"(mbar_a), "r"(phase) : "memory");
    if (!done) {
        asm volatile(
            "{\n\t.reg .pred P;\n"
            "WL_%=:\n\t"
            "mbarrier.try_wait.parity.acquire.cta.shared::cta.b64 P, [%0], %1, 0x989680;\n\t"
            "@P bra.uni WD_%=;\n\t"
            "bra.uni WL_%=;\n"
            "WD_%=:\n\t}"
            :: "r"(mbar_a), "r"(phase) : "memory");
    }
}

__global__ __launch_bounds__(NTHREADS, 1)
void logic_layer_kernel(const float* __restrict__ x,
                        float* __restrict__ out) {
    extern __shared__ float sx[];
    __shared__ __align__(8) uint64_t mbar;

    const int t = threadIdx.x;
    const uint32_t mbar_a = smem_u32(&mbar);
    const uint32_t dst_a  = smem_u32(sx);
    const uint2* packed2 = reinterpret_cast<const uint2*>(g_packed);

    if (t == 0) {
        asm volatile("mbarrier.init.shared.b64 [%0], 1;" :: "r"(mbar_a) : "memory");
        asm volatile("fence.proxy.async.shared::cta;" ::: "memory");
    }
    __syncthreads();

    // First fill for this CTA's first row.
    if (t == 0) {
        asm volatile("mbarrier.arrive.expect_tx.shared.b64 _, [%0], %1;"
                     :: "r"(mbar_a), "r"((uint32_t)(IN_DIM * 4)) : "memory");
        asm volatile("cp.async.bulk.shared::cta.global.mbarrier::complete_tx::bytes "
                     "[%0], [%1], %2, [%3];"
                     :: "r"(dst_a), "l"(x + (size_t)blockIdx.x * IN_DIM),
                        "r"((uint32_t)(IN_DIM * 4)), "r"(mbar_a)
                     : "memory");
    }

    uint32_t phase = 0;

    for (int row = blockIdx.x; row < BATCH; row += NSM) {
        // Pull this CTA's next row toward L2 while we work on this one.
        if (t == 32 && row + NSM < BATCH) {
            asm volatile("cp.async.bulk.prefetch.L2.global [%0], %1;"
                         :: "l"(x + (size_t)(row + NSM) * IN_DIM),
                            "r"((uint32_t)(IN_DIM * 4)) : "memory");
        }

        // Prime packed ring (gmem only) while the fill streams in.
        uint2 pr[4];
        #pragma unroll
        for (int k = 0; k < 4; k++) pr[k] = packed2[k * NTHREADS + t];

        mbar_wait(mbar_a, phase);
        phase ^= 1;

        float* orow = out + (size_t)row * OUT_DIM;

        #pragma unroll
        for (int k = 0; k < ITERS2; k++) {
            uint2 p = pr[k & 3];
            if (k + 4 < ITERS2) pr[k & 3] = packed2[(k + 4) * NTHREADS + t];
            float a0 = sx[(p.x >> 16) & 0x7FFFu];
            float b0 = sx[p.x & 0x7FFFu];
            float a1 = sx[(p.y >> 16) & 0x7FFFu];
            float b1 = sx[p.y & 0x7FFFu];
            if (p.x & 0x80000000u) a0 = 1.0f - a0;
            if (p.x & 0x00008000u) b0 = 1.0f - b0;
            if (p.y & 0x80000000u) a1 = 1.0f - a1;
            if (p.y & 0x00008000u) b1 = 1.0f - b1;
            stg_cs_v2(&orow[(size_t)k * NTHREADS * 2 + t * 2], a0 * b0, a1 * b1);
        }

        __syncthreads();  // all gathers of this row done reading sx

        // Kick the fill for this CTA's next row immediately.
        if (t == 0 && row + NSM < BATCH) {
            asm volatile("mbarrier.arrive.expect_tx.shared.b64 _, [%0], %1;"
                         :: "r"(mbar_a), "r"((uint32_t)(IN_DIM * 4)) : "memory");
            asm volatile("cp.async.bulk.shared::cta.global.mbarrier::complete_tx::bytes "
                         "[%0], [%1], %2, [%3];"
                         :: "r"(dst_a), "l"(x + (size_t)(row + NSM) * IN_DIM),
                            "r"((uint32_t)(IN_DIM * 4)), "r"(mbar_a)
                         : "memory");
        }
    }
}

extern "C" void kernel_launch(void* const* d_in, const int* in_sizes, int n_in,
                              void* d_out, int out_size) {
    const float* x      = (const float*)d_in[0];
    const float* logits = (const float*)d_in[1];
    const int*   idx_a  = (const int*)d_in[2];
    const int*   idx_b  = (const int*)d_in[3];
    float* out = (float*)d_out;

    cudaFuncSetAttribute(logic_layer_kernel,
                         cudaFuncAttributeMaxDynamicSharedMemorySize,
                         IN_DIM * (int)sizeof(float));

    prep_kernel<<<OUT_DIM / 256, 256>>>(logits, idx_a, idx_b);
    logic_layer_kernel<<<NSM, NTHREADS, IN_DIM * sizeof(float)>>>(x, out);
}